// round 8
// baseline (speedup 1.0000x reference)
#include <cuda_runtime.h>
#include <cuda_fp16.h>

#define TD    512   // timesteps
#define BD    512   // batch
#define HID   32    // hidden
#define G4    128   // 4*HID gate rows
#define EMBD  32
#define VOCAB 1000
#define FF    16
#define NCLS  7

// ---------------- scratch (static device globals; no runtime allocation) ----
// table layout: [v][unit][gate i,f,g,o]  (float4 per unit)
__device__ float g_table[VOCAB * G4];                       // 512 KB
__device__ float g_hs[(size_t)BD * TD * HID];               // 33.5 MB, (B,T,H)

// ---------------- packed f32x2 helpers -------------------------------------
__device__ __forceinline__ unsigned long long pk(float lo, float hi) {
    unsigned long long r;
    asm("mov.b64 %0, {%1,%2};" : "=l"(r) : "f"(lo), "f"(hi));
    return r;
}
__device__ __forceinline__ void upk(unsigned long long p, float& lo, float& hi) {
    asm("mov.b64 {%0,%1}, %2;" : "=f"(lo), "=f"(hi) : "l"(p));
}
__device__ __forceinline__ unsigned long long fma2(unsigned long long a,
                                                   unsigned long long b,
                                                   unsigned long long c) {
    unsigned long long d;
    asm("fma.rn.f32x2 %0, %1, %2, %3;" : "=l"(d) : "l"(a), "l"(b), "l"(c));
    return d;
}
__device__ __forceinline__ unsigned long long mul2(unsigned long long a,
                                                   unsigned long long b) {
    unsigned long long d;
    asm("mul.rn.f32x2 %0, %1, %2;" : "=l"(d) : "l"(a), "l"(b));
    return d;
}
__device__ __forceinline__ float tanh_ap(float x) {
    float y;
    asm("tanh.approx.f32 %0, %1;" : "=f"(y) : "f"(x));
    return y;
}
__device__ __forceinline__ unsigned long long tanh2(unsigned long long p) {
    float a, b; upk(p, a, b);
    return pk(tanh_ap(a), tanh_ap(b));
}
#define HALF2  0x3F0000003F000000ULL   // (0.5, 0.5)
#define SC_GO  0x3F0000003F800000ULL   // (1.0, 0.5)  g:tanh scale, o:sigmoid scale
#define BI_GO  0x3F00000000000000ULL   // (0.0, 0.5)

__device__ __forceinline__ __half2 u2h2(unsigned int u) {
    return *reinterpret_cast<__half2*>(&u);
}

// ---------------- K0: gate table  table[v][unit][gate] ----------------------
__global__ __launch_bounds__(256, 1)
void table_kernel(const float* __restrict__ emb,
                  const float* __restrict__ W_ih,
                  const float* __restrict__ b_ih,
                  const float* __restrict__ b_hh) {
    int tid  = threadIdx.x;
    int r    = tid & 127;        // gate-major row: gate = r>>5, unit = r&31
    int slot = tid >> 7;
    int v0   = blockIdx.x * 8;
    int gate = r >> 5, unit = r & 31;

    float4 w[8];
    const float4* wr = (const float4*)(W_ih + r * EMBD);
#pragma unroll
    for (int i = 0; i < 8; i++) w[i] = __ldg(wr + i);
    float bias = __ldg(b_ih + r) + __ldg(b_hh + r);

#pragma unroll
    for (int vo = 0; vo < 4; vo++) {
        int v = v0 + vo * 2 + slot;
        const float4* er = (const float4*)(emb + v * EMBD);
        float a0 = bias, a1 = 0.f, a2 = 0.f, a3 = 0.f;
#pragma unroll
        for (int i = 0; i < 8; i += 4) {
            float4 e0 = __ldg(er + i + 0);
            float4 e1 = __ldg(er + i + 1);
            float4 e2 = __ldg(er + i + 2);
            float4 e3 = __ldg(er + i + 3);
            a0 += w[i + 0].x * e0.x + w[i + 0].y * e0.y + w[i + 0].z * e0.z + w[i + 0].w * e0.w;
            a1 += w[i + 1].x * e1.x + w[i + 1].y * e1.y + w[i + 1].z * e1.z + w[i + 1].w * e1.w;
            a2 += w[i + 2].x * e2.x + w[i + 2].y * e2.y + w[i + 2].z * e2.z + w[i + 2].w * e2.w;
            a3 += w[i + 3].x * e3.x + w[i + 3].y * e3.y + w[i + 3].z * e3.z + w[i + 3].w * e3.w;
        }
        g_table[v * G4 + unit * 4 + gate] = (a0 + a1) + (a2 + a3);
    }
}

// ---------------- K1: LSTM — 2 batch elements per warp, interleaved ---------
// lane = hidden unit. Two independent recurrence chains share the same weight
// registers; their instruction streams interleave in the scheduler so each
// chain's dependency latency is hidden by the other's issue.
__global__ __launch_bounds__(128, 1)
void lstm_kernel(const int* __restrict__ x, const float* __restrict__ W_hh) {
    __shared__ __align__(16) __half2 hbuf[4][2][2][HID / 2]; // [warp][elem][parity][pair]
    int warp = threadIdx.x >> 5;
    int lane = threadIdx.x & 31;
    int b0   = blockIdx.x * 8 + warp * 2;
    int b1   = b0 + 1;

    // ---- shared weights: rows i,f,g,o for this unit as half2 pairs over h ----
    __half2 W2[4][HID / 2];                                  // 64 regs
#pragma unroll
    for (int g = 0; g < 4; g++) {
        const float4* p = (const float4*)(W_hh + (g * HID + lane) * HID);
#pragma unroll
        for (int i = 0; i < 8; i++) {
            float4 rv = __ldg(p + i);
            W2[g][2 * i + 0] = __floats2half2_rn(rv.x, rv.y);
            W2[g][2 * i + 1] = __floats2half2_rn(rv.z, rv.w);
        }
    }

    if (lane < HID / 2) {
        hbuf[warp][0][0][lane] = __float2half2_rn(0.f);
        hbuf[warp][0][1][lane] = __float2half2_rn(0.f);
        hbuf[warp][1][0][lane] = __float2half2_rn(0.f);
        hbuf[warp][1][1][lane] = __float2half2_rn(0.f);
    }
    __syncwarp();

    const float4* tab4 = (const float4*)g_table;   // 32 float4 per vocab row

    // pipelines per element: index depth 6, xg depth 3
    int A3 = x[0 * BD + b0], B3 = x[0 * BD + b1];
    int A4 = x[1 * BD + b0], B4 = x[1 * BD + b1];
    int A5 = x[2 * BD + b0], B5 = x[2 * BD + b1];
    float4 XA0 = __ldg(tab4 + A3 * 32 + lane), XB0 = __ldg(tab4 + B3 * 32 + lane);
    float4 XA1 = __ldg(tab4 + A4 * 32 + lane), XB1 = __ldg(tab4 + B4 * 32 + lane);
    float4 XA2 = __ldg(tab4 + A5 * 32 + lane), XB2 = __ldg(tab4 + B5 * 32 + lane);
    A3 = x[3 * BD + b0]; B3 = x[3 * BD + b1];
    A4 = x[4 * BD + b0]; B4 = x[4 * BD + b1];
    A5 = x[5 * BD + b0]; B5 = x[5 * BD + b1];

    float cA = 0.f, cB = 0.f;
    float* hsA = g_hs + (size_t)b0 * TD * HID;
    float* hsB = g_hs + (size_t)b1 * TD * HID;

    for (int t = 0; t < TD; t++) {
        // prefetch xg for t+3, index for t+6 (both elements)
        float4 nxa = __ldg(tab4 + A3 * 32 + lane);
        float4 nxb = __ldg(tab4 + B3 * 32 + lane);
        int nA = 0, nB = 0;
        if (t + 6 < TD) { nA = x[(t + 6) * BD + b0]; nB = x[(t + 6) * BD + b1]; }

        // load h tiles for both elements (4+4 LDS.128, broadcast)
        const uint4* hqA = (const uint4*)hbuf[warp][0][t & 1];
        const uint4* hqB = (const uint4*)hbuf[warp][1][t & 1];
        uint4 qa0 = hqA[0], qa1 = hqA[1], qa2 = hqA[2], qa3 = hqA[3];
        uint4 qb0 = hqB[0], qb1 = hqB[1], qb2 = hqB[2], qb3 = hqB[3];
        __half2 hA[HID / 2], hB[HID / 2];
        hA[0]  = u2h2(qa0.x); hA[1]  = u2h2(qa0.y); hA[2]  = u2h2(qa0.z); hA[3]  = u2h2(qa0.w);
        hA[4]  = u2h2(qa1.x); hA[5]  = u2h2(qa1.y); hA[6]  = u2h2(qa1.z); hA[7]  = u2h2(qa1.w);
        hA[8]  = u2h2(qa2.x); hA[9]  = u2h2(qa2.y); hA[10] = u2h2(qa2.z); hA[11] = u2h2(qa2.w);
        hA[12] = u2h2(qa3.x); hA[13] = u2h2(qa3.y); hA[14] = u2h2(qa3.z); hA[15] = u2h2(qa3.w);
        hB[0]  = u2h2(qb0.x); hB[1]  = u2h2(qb0.y); hB[2]  = u2h2(qb0.z); hB[3]  = u2h2(qb0.w);
        hB[4]  = u2h2(qb1.x); hB[5]  = u2h2(qb1.y); hB[6]  = u2h2(qb1.z); hB[7]  = u2h2(qb1.w);
        hB[8]  = u2h2(qb2.x); hB[9]  = u2h2(qb2.y); hB[10] = u2h2(qb2.z); hB[11] = u2h2(qb2.w);
        hB[12] = u2h2(qb3.x); hB[13] = u2h2(qb3.y); hB[14] = u2h2(qb3.z); hB[15] = u2h2(qb3.w);

        // interleaved dot products: 8 chains per element, depth 8
        __half2 z = __float2half2_rn(0.f);
        __half2 aAA[4] = {z, z, z, z}, aAB[4] = {z, z, z, z};
        __half2 aBA[4] = {z, z, z, z}, aBB[4] = {z, z, z, z};
#pragma unroll
        for (int k = 0; k < 8; k++) {
#pragma unroll
            for (int g = 0; g < 4; g++) {
                aAA[g] = __hfma2(W2[g][k],     hA[k],     aAA[g]);
                aBA[g] = __hfma2(W2[g][k],     hB[k],     aBA[g]);
                aAB[g] = __hfma2(W2[g][k + 8], hA[k + 8], aAB[g]);
                aBB[g] = __hfma2(W2[g][k + 8], hB[k + 8], aBB[g]);
            }
        }
        float2 fiA = __half22float2(__hadd2(aAA[0], aAB[0]));
        float2 ffA = __half22float2(__hadd2(aAA[1], aAB[1]));
        float2 fgA = __half22float2(__hadd2(aAA[2], aAB[2]));
        float2 foA = __half22float2(__hadd2(aAA[3], aAB[3]));
        float2 fiB = __half22float2(__hadd2(aBA[0], aBB[0]));
        float2 ffB = __half22float2(__hadd2(aBA[1], aBB[1]));
        float2 fgB = __half22float2(__hadd2(aBA[2], aBB[2]));
        float2 foB = __half22float2(__hadd2(aBA[3], aBB[3]));

        unsigned long long aifA = pk(XA0.x + fiA.x + fiA.y, XA0.y + ffA.x + ffA.y);
        unsigned long long agoA = pk(XA0.z + fgA.x + fgA.y, XA0.w + foA.x + foA.y);
        unsigned long long aifB = pk(XB0.x + fiB.x + fiB.y, XB0.y + ffB.x + ffB.y);
        unsigned long long agoB = pk(XB0.z + fgB.x + fgB.y, XB0.w + foB.x + foB.y);

        unsigned long long sifA = fma2(tanh2(mul2(aifA, HALF2)), HALF2, HALF2);
        unsigned long long sgoA = fma2(tanh2(mul2(agoA, SC_GO)), SC_GO, BI_GO);
        unsigned long long sifB = fma2(tanh2(mul2(aifB, HALF2)), HALF2, HALF2);
        unsigned long long sgoB = fma2(tanh2(mul2(agoB, SC_GO)), SC_GO, BI_GO);

        float ivA, fvA, gvA, ovA, ivB, fvB, gvB, ovB;
        upk(sifA, ivA, fvA); upk(sgoA, gvA, ovA);
        upk(sifB, ivB, fvB); upk(sgoB, gvB, ovB);

        cA = fmaf(fvA, cA, ivA * gvA);
        cB = fmaf(fvB, cB, ivB * gvB);
        float hA_new = ovA * tanh_ap(cA);
        float hB_new = ovB * tanh_ap(cB);

        ((__half*)hbuf[warp][0][(t + 1) & 1])[lane] = __float2half_rn(hA_new);
        ((__half*)hbuf[warp][1][(t + 1) & 1])[lane] = __float2half_rn(hB_new);
        hsA[t * HID + lane] = hA_new;
        hsB[t * HID + lane] = hB_new;
        __syncwarp();

        XA0 = XA1; XA1 = XA2; XA2 = nxa;
        XB0 = XB1; XB1 = XB2; XB2 = nxb;
        A3 = A4; A4 = A5; A5 = nA;
        B3 = B4; B4 = B5; B5 = nB;
    }
}

// ---------------- K2: fused FF head + softmax over T ------------------------
__global__ __launch_bounds__(256, 1)
void head_softmax_kernel(const float* __restrict__ W1, const float* __restrict__ b1,
                         const float* __restrict__ W2, const float* __restrict__ b2,
                         float* __restrict__ out) {
    __shared__ unsigned long long W1p[FF * HID];
    __shared__ unsigned long long W2p[NCLS * FF];
    __shared__ float b1s[FF], b2s[NCLS];
    __shared__ float wredm[8][NCLS], wreds[8][NCLS];

    int tid = threadIdx.x;
    for (int i = tid; i < FF * HID; i += 256) { float w = W1[i]; W1p[i] = pk(w, w); }
    if (tid < NCLS * FF) { float w = W2[tid]; W2p[tid] = pk(w, w); }
    if (tid < FF)   b1s[tid] = b1[tid];
    if (tid < NCLS) b2s[tid] = b2[tid];
    __syncthreads();

    int b  = blockIdx.x;
    int t0 = tid * 2;
    const float* hr = g_hs + ((size_t)b * TD + t0) * HID;

    unsigned long long h2[HID];
#pragma unroll
    for (int k4 = 0; k4 < HID / 4; k4++) {
        float4 u = ((const float4*)hr)[k4];
        float4 v = ((const float4*)(hr + HID))[k4];
        h2[k4 * 4 + 0] = pk(u.x, v.x);
        h2[k4 * 4 + 1] = pk(u.y, v.y);
        h2[k4 * 4 + 2] = pk(u.z, v.z);
        h2[k4 * 4 + 3] = pk(u.w, v.w);
    }

    unsigned long long z2[FF];
#pragma unroll
    for (int f = 0; f < FF; f++) {
        unsigned long long acc = pk(b1s[f], b1s[f]);
#pragma unroll
        for (int k = 0; k < HID; k++) acc = fma2(W1p[f * HID + k], h2[k], acc);
        float lo, hi; upk(acc, lo, hi);
        z2[f] = pk(fmaxf(lo, 0.f), fmaxf(hi, 0.f));
    }

    float va[NCLS], vb[NCLS];
#pragma unroll
    for (int c = 0; c < NCLS; c++) {
        unsigned long long acc = pk(b2s[c], b2s[c]);
#pragma unroll
        for (int k = 0; k < FF; k++) acc = fma2(W2p[c * FF + k], z2[k], acc);
        upk(acc, va[c], vb[c]);
    }

    // --- softmax over T (across the whole CTA) ---
    int wid = tid >> 5, lid = tid & 31;
    float vm[NCLS];
#pragma unroll
    for (int c = 0; c < NCLS; c++) vm[c] = fmaxf(va[c], vb[c]);
#pragma unroll
    for (int off = 16; off; off >>= 1)
#pragma unroll
        for (int c = 0; c < NCLS; c++)
            vm[c] = fmaxf(vm[c], __shfl_xor_sync(0xffffffffu, vm[c], off));
    if (lid == 0)
#pragma unroll
        for (int c = 0; c < NCLS; c++) wredm[wid][c] = vm[c];
    __syncthreads();
    float gmax[NCLS];
#pragma unroll
    for (int c = 0; c < NCLS; c++) {
        float m = wredm[0][c];
#pragma unroll
        for (int w = 1; w < 8; w++) m = fmaxf(m, wredm[w][c]);
        gmax[c] = m;
    }
    float sm[NCLS];
#pragma unroll
    for (int c = 0; c < NCLS; c++) {
        va[c] = __expf(va[c] - gmax[c]);
        vb[c] = __expf(vb[c] - gmax[c]);
        sm[c] = va[c] + vb[c];
    }
#pragma unroll
    for (int off = 16; off; off >>= 1)
#pragma unroll
        for (int c = 0; c < NCLS; c++)
            sm[c] += __shfl_xor_sync(0xffffffffu, sm[c], off);
    if (lid == 0)
#pragma unroll
        for (int c = 0; c < NCLS; c++) wreds[wid][c] = sm[c];
    __syncthreads();
    float inv[NCLS];
#pragma unroll
    for (int c = 0; c < NCLS; c++) {
        float s = wreds[0][c];
#pragma unroll
        for (int w = 1; w < 8; w++) s += wreds[w][c];
        inv[c] = 1.0f / s;
    }

    float* o0 = out + (size_t)t0 * BD * NCLS + (size_t)b * NCLS;
#pragma unroll
    for (int c = 0; c < NCLS; c++) o0[c] = va[c] * inv[c];
#pragma unroll
    for (int c = 0; c < NCLS; c++) o0[BD * NCLS + c] = vb[c] * inv[c];
}

// ---------------- launch -----------------------------------------------------
extern "C" void kernel_launch(void* const* d_in, const int* in_sizes, int n_in,
                              void* d_out, int out_size) {
    (void)in_sizes; (void)n_in; (void)out_size;
    const int*   x    = (const int*)  d_in[0];
    const float* emb  = (const float*)d_in[1];
    const float* W_ih = (const float*)d_in[2];
    const float* W_hh = (const float*)d_in[3];
    const float* b_ih = (const float*)d_in[4];
    const float* b_hh = (const float*)d_in[5];
    const float* W1   = (const float*)d_in[6];
    const float* b1   = (const float*)d_in[7];
    const float* W2   = (const float*)d_in[8];
    const float* b2   = (const float*)d_in[9];

    table_kernel<<<VOCAB / 8, 256>>>(emb, W_ih, b_ih, b_hh);
    lstm_kernel<<<BD / 8, 128>>>(x, W_hh);
    head_softmax_kernel<<<BD, 256>>>(W1, b1, W2, b2, (float*)d_out);
}

// round 12
// speedup vs baseline: 1.9479x; 1.9479x over previous
#include <cuda_runtime.h>
#include <cuda_fp16.h>

#define TD    512   // timesteps
#define BD    512   // batch
#define HID   32    // hidden
#define G4    128   // 4*HID gate rows
#define EMBD  32
#define VOCAB 1000
#define FF    16
#define NCLS  7

// ---------------- scratch (static device globals; no runtime allocation) ----
// table layout: [v][unit][gate i,f,g,o]  (float4 per unit)
__device__ float g_table[VOCAB * G4];                       // 512 KB
__device__ float g_hs[(size_t)BD * TD * HID];               // 33.5 MB, (B,T,H)

// ---------------- helpers ---------------------------------------------------
__device__ __forceinline__ unsigned long long pk(float lo, float hi) {
    unsigned long long r;
    asm("mov.b64 %0, {%1,%2};" : "=l"(r) : "f"(lo), "f"(hi));
    return r;
}
__device__ __forceinline__ void upk(unsigned long long p, float& lo, float& hi) {
    asm("mov.b64 {%0,%1}, %2;" : "=f"(lo), "=f"(hi) : "l"(p));
}
__device__ __forceinline__ unsigned long long fma2(unsigned long long a,
                                                   unsigned long long b,
                                                   unsigned long long c) {
    unsigned long long d;
    asm("fma.rn.f32x2 %0, %1, %2, %3;" : "=l"(d) : "l"(a), "l"(b), "l"(c));
    return d;
}
__device__ __forceinline__ float tanh_ap(float x) {
    float y;
    asm("tanh.approx.f32 %0, %1;" : "=f"(y) : "f"(x));
    return y;
}
__device__ __forceinline__ float sigmoid_ap(float x) {
    return fmaf(tanh_ap(0.5f * x), 0.5f, 0.5f);
}
__device__ __forceinline__ __half2 u2h2(unsigned int u) {
    return *reinterpret_cast<__half2*>(&u);
}

// ---------------- K0: gate table  table[v][unit][gate] ----------------------
__global__ __launch_bounds__(256, 1)
void table_kernel(const float* __restrict__ emb,
                  const float* __restrict__ W_ih,
                  const float* __restrict__ b_ih,
                  const float* __restrict__ b_hh) {
    int tid  = threadIdx.x;
    int r    = tid & 127;        // gate-major row: gate = r>>5, unit = r&31
    int slot = tid >> 7;
    int v0   = blockIdx.x * 8;
    int gate = r >> 5, unit = r & 31;

    float4 w[8];
    const float4* wr = (const float4*)(W_ih + r * EMBD);
#pragma unroll
    for (int i = 0; i < 8; i++) w[i] = __ldg(wr + i);
    float bias = __ldg(b_ih + r) + __ldg(b_hh + r);

#pragma unroll
    for (int vo = 0; vo < 4; vo++) {
        int v = v0 + vo * 2 + slot;
        const float4* er = (const float4*)(emb + v * EMBD);
        float a0 = bias, a1 = 0.f, a2 = 0.f, a3 = 0.f;
#pragma unroll
        for (int i = 0; i < 8; i += 4) {
            float4 e0 = __ldg(er + i + 0);
            float4 e1 = __ldg(er + i + 1);
            float4 e2 = __ldg(er + i + 2);
            float4 e3 = __ldg(er + i + 3);
            a0 += w[i + 0].x * e0.x + w[i + 0].y * e0.y + w[i + 0].z * e0.z + w[i + 0].w * e0.w;
            a1 += w[i + 1].x * e1.x + w[i + 1].y * e1.y + w[i + 1].z * e1.z + w[i + 1].w * e1.w;
            a2 += w[i + 2].x * e2.x + w[i + 2].y * e2.y + w[i + 2].z * e2.z + w[i + 2].w * e2.w;
            a3 += w[i + 3].x * e3.x + w[i + 3].y * e3.y + w[i + 3].z * e3.z + w[i + 3].w * e3.w;
        }
        g_table[v * G4 + unit * 4 + gate] = (a0 + a1) + (a2 + a3);
    }
}

// ---------------- K1: LSTM — one warp per batch element, fp16 dot -----------
// lane = hidden unit. Critical-path-minimized: depth-4 HFMA2 chains (16
// accumulators), scalar MUFU activations, h via smem double buffer+syncwarp.
__global__ __launch_bounds__(128, 1)
void lstm_kernel(const int* __restrict__ x, const float* __restrict__ W_hh) {
    __shared__ __align__(16) __half2 hbuf[4][2][HID / 2];   // [warp][parity][pair]
    int warp = threadIdx.x >> 5;
    int lane = threadIdx.x & 31;
    int b    = blockIdx.x * 4 + warp;

    // ---- weights: rows i,f,g,o for this unit as half2 pairs over h ----
    __half2 W2[4][HID / 2];                                  // 64 regs
#pragma unroll
    for (int g = 0; g < 4; g++) {
        const float4* p = (const float4*)(W_hh + (g * HID + lane) * HID);
#pragma unroll
        for (int i = 0; i < 8; i++) {
            float4 rv = __ldg(p + i);
            W2[g][2 * i + 0] = __floats2half2_rn(rv.x, rv.y);
            W2[g][2 * i + 1] = __floats2half2_rn(rv.z, rv.w);
        }
    }

    if (lane < HID / 2) {
        hbuf[warp][0][lane] = __float2half2_rn(0.f);
        hbuf[warp][1][lane] = __float2half2_rn(0.f);
    }
    __syncwarp();

    const float4* tab4 = (const float4*)g_table;   // 32 float4 per vocab row

    // pipelines: index depth 6, xg depth 3
    int I3 = x[0 * BD + b];
    int I4 = x[1 * BD + b];
    int I5 = x[2 * BD + b];
    float4 XG0 = __ldg(tab4 + I3 * 32 + lane);   // t=0  (i,f,g,o)
    float4 XG1 = __ldg(tab4 + I4 * 32 + lane);   // t=1
    float4 XG2 = __ldg(tab4 + I5 * 32 + lane);   // t=2
    I3 = x[3 * BD + b];
    I4 = x[4 * BD + b];
    I5 = x[5 * BD + b];

    float c = 0.f;
    float* hs = g_hs + (size_t)b * TD * HID;

    for (int t = 0; t < TD; t++) {
        // prefetch xg for t+3 (2 bodies of slack), index for t+6
        float4 nxg = __ldg(tab4 + I3 * 32 + lane);
        int nI = 0;
        if (t + 6 < TD) nI = x[(t + 6) * BD + b];

        // load h (16 half2 = 4 x LDS.128, broadcast)
        const uint4* hq = (const uint4*)hbuf[warp][t & 1];
        uint4 q0 = hq[0], q1 = hq[1], q2 = hq[2], q3 = hq[3];
        __half2 h2[HID / 2];
        h2[0]  = u2h2(q0.x); h2[1]  = u2h2(q0.y); h2[2]  = u2h2(q0.z); h2[3]  = u2h2(q0.w);
        h2[4]  = u2h2(q1.x); h2[5]  = u2h2(q1.y); h2[6]  = u2h2(q1.z); h2[7]  = u2h2(q1.w);
        h2[8]  = u2h2(q2.x); h2[9]  = u2h2(q2.y); h2[10] = u2h2(q2.z); h2[11] = u2h2(q2.w);
        h2[12] = u2h2(q3.x); h2[13] = u2h2(q3.y); h2[14] = u2h2(q3.z); h2[15] = u2h2(q3.w);

        // 16 independent HFMA2 chains (4 per gate, depth 4)
        __half2 z = __float2half2_rn(0.f);
        __half2 acc[4][4] = {{z, z, z, z}, {z, z, z, z}, {z, z, z, z}, {z, z, z, z}};
#pragma unroll
        for (int k = 0; k < 4; k++) {
#pragma unroll
            for (int g = 0; g < 4; g++) {
                acc[g][0] = __hfma2(W2[g][k],      h2[k],      acc[g][0]);
                acc[g][1] = __hfma2(W2[g][k + 4],  h2[k + 4],  acc[g][1]);
                acc[g][2] = __hfma2(W2[g][k + 8],  h2[k + 8],  acc[g][2]);
                acc[g][3] = __hfma2(W2[g][k + 12], h2[k + 12], acc[g][3]);
            }
        }
        // fold trees (half), then fp32 combine with xg
        float2 fi = __half22float2(__hadd2(__hadd2(acc[0][0], acc[0][1]),
                                           __hadd2(acc[0][2], acc[0][3])));
        float2 ff = __half22float2(__hadd2(__hadd2(acc[1][0], acc[1][1]),
                                           __hadd2(acc[1][2], acc[1][3])));
        float2 fg = __half22float2(__hadd2(__hadd2(acc[2][0], acc[2][1]),
                                           __hadd2(acc[2][2], acc[2][3])));
        float2 fo = __half22float2(__hadd2(__hadd2(acc[3][0], acc[3][1]),
                                           __hadd2(acc[3][2], acc[3][3])));
        float ai = XG0.x + (fi.x + fi.y);
        float af = XG0.y + (ff.x + ff.y);
        float ag = XG0.z + (fg.x + fg.y);
        float ao = XG0.w + (fo.x + fo.y);

        // scalar activations — all four MUFU-parallel, shortest serial chain
        float iv = sigmoid_ap(ai);
        float fv = sigmoid_ap(af);
        float gv = tanh_ap(ag);
        float ov = sigmoid_ap(ao);

        c = fmaf(fv, c, iv * gv);          // c = f*c + i*g
        float h = ov * tanh_ap(c);         // h = o*tanh(c)

        ((__half*)hbuf[warp][(t + 1) & 1])[lane] = __float2half_rn(h);
        hs[t * HID + lane] = h;            // coalesced 128B per warp
        __syncwarp();

        XG0 = XG1; XG1 = XG2; XG2 = nxg;
        I3 = I4; I4 = I5; I5 = nI;
    }
}

// ---------------- K2: fused FF head + softmax over T ------------------------
__global__ __launch_bounds__(256, 1)
void head_softmax_kernel(const float* __restrict__ W1, const float* __restrict__ b1,
                         const float* __restrict__ W2, const float* __restrict__ b2,
                         float* __restrict__ out) {
    __shared__ unsigned long long W1p[FF * HID];
    __shared__ unsigned long long W2p[NCLS * FF];
    __shared__ float b1s[FF], b2s[NCLS];
    __shared__ float wredm[8][NCLS], wreds[8][NCLS];

    int tid = threadIdx.x;
    for (int i = tid; i < FF * HID; i += 256) { float w = W1[i]; W1p[i] = pk(w, w); }
    if (tid < NCLS * FF) { float w = W2[tid]; W2p[tid] = pk(w, w); }
    if (tid < FF)   b1s[tid] = b1[tid];
    if (tid < NCLS) b2s[tid] = b2[tid];
    __syncthreads();

    int b  = blockIdx.x;
    int t0 = tid * 2;
    const float* hr = g_hs + ((size_t)b * TD + t0) * HID;

    unsigned long long h2[HID];
#pragma unroll
    for (int k4 = 0; k4 < HID / 4; k4++) {
        float4 u = ((const float4*)hr)[k4];
        float4 v = ((const float4*)(hr + HID))[k4];
        h2[k4 * 4 + 0] = pk(u.x, v.x);
        h2[k4 * 4 + 1] = pk(u.y, v.y);
        h2[k4 * 4 + 2] = pk(u.z, v.z);
        h2[k4 * 4 + 3] = pk(u.w, v.w);
    }

    unsigned long long z2[FF];
#pragma unroll
    for (int f = 0; f < FF; f++) {
        unsigned long long acc = pk(b1s[f], b1s[f]);
#pragma unroll
        for (int k = 0; k < HID; k++) acc = fma2(W1p[f * HID + k], h2[k], acc);
        float lo, hi; upk(acc, lo, hi);
        z2[f] = pk(fmaxf(lo, 0.f), fmaxf(hi, 0.f));
    }

    float va[NCLS], vb[NCLS];
#pragma unroll
    for (int c = 0; c < NCLS; c++) {
        unsigned long long acc = pk(b2s[c], b2s[c]);
#pragma unroll
        for (int k = 0; k < FF; k++) acc = fma2(W2p[c * FF + k], z2[k], acc);
        upk(acc, va[c], vb[c]);
    }

    // --- softmax over T (across the whole CTA) ---
    int wid = tid >> 5, lid = tid & 31;
    float vm[NCLS];
#pragma unroll
    for (int c = 0; c < NCLS; c++) vm[c] = fmaxf(va[c], vb[c]);
#pragma unroll
    for (int off = 16; off; off >>= 1)
#pragma unroll
        for (int c = 0; c < NCLS; c++)
            vm[c] = fmaxf(vm[c], __shfl_xor_sync(0xffffffffu, vm[c], off));
    if (lid == 0)
#pragma unroll
        for (int c = 0; c < NCLS; c++) wredm[wid][c] = vm[c];
    __syncthreads();
    float gmax[NCLS];
#pragma unroll
    for (int c = 0; c < NCLS; c++) {
        float m = wredm[0][c];
#pragma unroll
        for (int w = 1; w < 8; w++) m = fmaxf(m, wredm[w][c]);
        gmax[c] = m;
    }
    float sm[NCLS];
#pragma unroll
    for (int c = 0; c < NCLS; c++) {
        va[c] = __expf(va[c] - gmax[c]);
        vb[c] = __expf(vb[c] - gmax[c]);
        sm[c] = va[c] + vb[c];
    }
#pragma unroll
    for (int off = 16; off; off >>= 1)
#pragma unroll
        for (int c = 0; c < NCLS; c++)
            sm[c] += __shfl_xor_sync(0xffffffffu, sm[c], off);
    if (lid == 0)
#pragma unroll
        for (int c = 0; c < NCLS; c++) wreds[wid][c] = sm[c];
    __syncthreads();
    float inv[NCLS];
#pragma unroll
    for (int c = 0; c < NCLS; c++) {
        float s = wreds[0][c];
#pragma unroll
        for (int w = 1; w < 8; w++) s += wreds[w][c];
        inv[c] = 1.0f / s;
    }

    float* o0 = out + (size_t)t0 * BD * NCLS + (size_t)b * NCLS;
#pragma unroll
    for (int c = 0; c < NCLS; c++) o0[c] = va[c] * inv[c];
#pragma unroll
    for (int c = 0; c < NCLS; c++) o0[BD * NCLS + c] = vb[c] * inv[c];
}

// ---------------- launch -----------------------------------------------------
extern "C" void kernel_launch(void* const* d_in, const int* in_sizes, int n_in,
                              void* d_out, int out_size) {
    (void)in_sizes; (void)n_in; (void)out_size;
    const int*   x    = (const int*)  d_in[0];
    const float* emb  = (const float*)d_in[1];
    const float* W_ih = (const float*)d_in[2];
    const float* W_hh = (const float*)d_in[3];
    const float* b_ih = (const float*)d_in[4];
    const float* b_hh = (const float*)d_in[5];
    const float* W1   = (const float*)d_in[6];
    const float* b1   = (const float*)d_in[7];
    const float* W2   = (const float*)d_in[8];
    const float* b2   = (const float*)d_in[9];

    table_kernel<<<VOCAB / 8, 256>>>(emb, W_ih, b_ih, b_hh);
    lstm_kernel<<<BD / 4, 128>>>(x, W_hh);
    head_softmax_kernel<<<BD, 256>>>(W1, b1, W2, b2, (float*)d_out);
}